// round 4
// baseline (speedup 1.0000x reference)
#include <cuda_runtime.h>

// Fixed problem shape
#define BB    4
#define CC    256
#define HH    128
#define WW    256
#define NGRP  4
#define CG    64
#define WIN   9
#define CK    16                 // channels per pipeline stage
#define SRS   264                // padded smem row stride (pixel w at col w+4)
#define NCHUNK (CC / CK)         // 16 chunks
#define NSTAGE 3                 // ring depth
#define STAGE_F (2 * CK * SRS)   // floats per stage: srw[CK][SRS] + slf[CK][SRS]

__global__ __launch_bounds__(512, 2)
void crestereo_pc_kernel(const float* __restrict__ left,
                         const float* __restrict__ right,
                         const float* __restrict__ flow,
                         float* __restrict__ out)
{
    extern __shared__ float sm[];

    const int bh = blockIdx.x;
    const int b  = bh >> 7;          // bh / HH
    const int h  = bh & (HH - 1);
    const int tid = threadIdx.x;
    const int HW = HH * WW;

    if (tid < 256) {
        // ================= PRODUCER (warps 0-7): bilinear gather + left staging =================
        const int w = tid;

        const float fx = flow[(((size_t)b * 2 + 0) * HH + h) * WW + w];
        const float fy = flow[(((size_t)b * 2 + 1) * HH + h) * WW + w];
        const float x = (float)w + fx;
        const float y = (float)h + fy;
        const float x0f = floorf(x);
        const float y0f = floorf(y);
        const int ix0 = (int)x0f;
        const int iy0 = (int)y0f;
        const float ax = x - x0f;
        const float ay = y - y0f;

        float w00 = (1.f - ax) * (1.f - ay);
        float w01 = ax * (1.f - ay);
        float w10 = (1.f - ax) * ay;
        float w11 = ax * ay;

        const bool vx0 = (ix0     >= 0) & (ix0     <= WW - 1);
        const bool vx1 = (ix0 + 1 >= 0) & (ix0 + 1 <= WW - 1);
        const bool vy0 = (iy0     >= 0) & (iy0     <= HH - 1);
        const bool vy1 = (iy0 + 1 >= 0) & (iy0 + 1 <= HH - 1);
        if (!(vx0 & vy0)) w00 = 0.f;
        if (!(vx1 & vy0)) w01 = 0.f;
        if (!(vx0 & vy1)) w10 = 0.f;
        if (!(vx1 & vy1)) w11 = 0.f;

        const int x0c = min(max(ix0, 0), WW - 1);
        const int x1c = min(max(ix0 + 1, 0), WW - 1);
        const int y0c = min(max(iy0, 0), HH - 1);
        const int y1c = min(max(iy0 + 1, 0), HH - 1);

        const int o00 = y0c * WW + x0c;
        const int o01 = y0c * WW + x1c;
        const int o10 = y1c * WW + x0c;
        const int o11 = y1c * WW + x1c;

        const float* rbase = right + (size_t)b * CC * HW;
        const float* lrow  = left  + (size_t)b * CC * HW + (size_t)h * WW + w;

        for (int c = 0; c < NCHUNK; ++c) {
            const int s = c % NSTAGE;
            if (c >= NSTAGE)   // wait for consumer to free this stage
                asm volatile("bar.sync %0, 512;" :: "r"(4 + s) : "memory");

            float* srw = sm + s * STAGE_F;          // [CK][SRS]
            float* slf = srw + CK * SRS;            // [CK][SRS]
            const int ch0 = c * CK;

#pragma unroll 8
            for (int cc = 0; cc < CK; ++cc) {
                const float* rb = rbase + (size_t)(ch0 + cc) * HW;
                float v = rb[o00] * w00;
                v = fmaf(rb[o01], w01, v);
                v = fmaf(rb[o10], w10, v);
                v = fmaf(rb[o11], w11, v);
                srw[cc * SRS + 4 + w] = v;
                if (w == 0) {
                    srw[cc * SRS + 0] = v; srw[cc * SRS + 1] = v;
                    srw[cc * SRS + 2] = v; srw[cc * SRS + 3] = v;
                }
                if (w == WW - 1) {
                    srw[cc * SRS + WW + 4] = v; srw[cc * SRS + WW + 5] = v;
                    srw[cc * SRS + WW + 6] = v; srw[cc * SRS + WW + 7] = v;
                }
                slf[cc * SRS + w] = lrow[(size_t)(ch0 + cc) * HW];
            }
            asm volatile("bar.arrive %0, 512;" :: "r"(1 + s) : "memory");  // stage FULL
        }
    } else {
        // ================= CONSUMER (warps 8-15): pixel-pair correlation =================
        const int ct = tid - 256;        // logical pixel-pair lane
        const int pg = ct >> 1;          // pixel pair -> pixels 2pg, 2pg+1
        const int cs = ct & 1;           // channel parity

        float acc0[WIN], acc1[WIN];
#pragma unroll
        for (int k = 0; k < WIN; ++k) { acc0[k] = 0.f; acc1[k] = 0.f; }

        const float scale = 1.f / (float)CG;

        for (int c = 0; c < NCHUNK; ++c) {
            const int s = c % NSTAGE;
            asm volatile("bar.sync %0, 512;" :: "r"(1 + s) : "memory");   // wait FULL

            const float* srw = sm + s * STAGE_F;
            const float* slf = srw + CK * SRS;

#pragma unroll
            for (int i = 0; i < CK / 2; ++i) {
                const int cc = 2 * i + cs;
                const float2 lv = *(const float2*)(slf + cc * SRS + 2 * pg);
                float t[10];
#pragma unroll
                for (int j = 0; j < 5; ++j) {
                    const float2 d = *(const float2*)(srw + cc * SRS + 2 * pg + 2 * j);
                    t[2 * j]     = d.x;
                    t[2 * j + 1] = d.y;
                }
#pragma unroll
                for (int k = 0; k < WIN; ++k) {
                    acc0[k] = fmaf(lv.x, t[k],     acc0[k]);
                    acc1[k] = fmaf(lv.y, t[k + 1], acc1[k]);
                }
            }

            if (c + NSTAGE < NCHUNK)   // stage EMPTY (skip unmatched trailing arrives)
                asm volatile("bar.arrive %0, 512;" :: "r"(4 + s) : "memory");

            if ((c & 3) == 3) {        // group boundary: merge parities + write 9 taps
                const int g = c >> 2;
#pragma unroll
                for (int k = 0; k < WIN; ++k) {
                    acc0[k] += __shfl_xor_sync(0xffffffffu, acc0[k], 1);
                    acc1[k] += __shfl_xor_sync(0xffffffffu, acc1[k], 1);
                }
                // even lane writes pixel 2pg (acc0), odd lane pixel 2pg+1 (acc1): col == ct
                float* ob = out + (((size_t)(b * NGRP + g) * WIN) * HH + h) * WW + ct;
#pragma unroll
                for (int k = 0; k < WIN; ++k)
                    ob[(size_t)k * HW] = (cs ? acc1[k] : acc0[k]) * scale;
#pragma unroll
                for (int k = 0; k < WIN; ++k) { acc0[k] = 0.f; acc1[k] = 0.f; }
            }
        }
    }
}

extern "C" void kernel_launch(void* const* d_in, const int* in_sizes, int n_in,
                              void* d_out, int out_size)
{
    const float* left  = (const float*)d_in[0];
    const float* right = (const float*)d_in[1];
    const float* flow  = (const float*)d_in[2];
    float* out = (float*)d_out;

    const int smem_bytes = NSTAGE * STAGE_F * (int)sizeof(float);  // 101,376 B
    cudaFuncSetAttribute(crestereo_pc_kernel,
                         cudaFuncAttributeMaxDynamicSharedMemorySize, smem_bytes);

    dim3 grid(BB * HH);    // 512 blocks: one per (b, h) row
    dim3 block(512);       // 8 producer warps + 8 consumer warps
    crestereo_pc_kernel<<<grid, block, smem_bytes>>>(left, right, flow, out);
}

// round 5
// speedup vs baseline: 1.0892x; 1.0892x over previous
#include <cuda_runtime.h>

// Fixed problem shape
#define BB    4
#define CC    256
#define HH    128
#define WW    256
#define NGRP  4
#define CG    64
#define WIN   9
#define CK    32                // channels per pipeline chunk
#define SRS   264               // padded smem row: pixel w lives at col w+4
#define NCHUNK (CC / CK)        // 8 chunks; 2 chunks per group

__device__ __forceinline__
void gather_chunk(const float* __restrict__ rbase, float* __restrict__ dst,
                  int ch0, int w, int HW,
                  int o00, int o01, int o10, int o11,
                  float w00, float w01, float w10, float w11)
{
#pragma unroll
    for (int cc = 0; cc < CK; ++cc) {
        const float* rb = rbase + (size_t)(ch0 + cc) * HW;
        float v = rb[o00] * w00;
        v = fmaf(rb[o01], w01, v);
        v = fmaf(rb[o10], w10, v);
        v = fmaf(rb[o11], w11, v);
        float* row = dst + cc * SRS;
        row[4 + w] = v;
        if (w == 0) {
            row[0] = v; row[1] = v; row[2] = v; row[3] = v;
        }
        if (w == WW - 1) {
            row[WW + 4] = v; row[WW + 5] = v; row[WW + 6] = v; row[WW + 7] = v;
        }
    }
}

__global__ __launch_bounds__(256, 3)
void crestereo_db_kernel(const float* __restrict__ left,
                         const float* __restrict__ right,
                         const float* __restrict__ flow,
                         float* __restrict__ out)
{
    extern __shared__ float smbuf[];          // [2][CK][SRS]
    float* buf0 = smbuf;
    float* buf1 = smbuf + CK * SRS;

    const int bh = blockIdx.x;
    const int b  = bh >> 7;                   // bh / HH
    const int h  = bh & (HH - 1);
    const int w  = threadIdx.x;
    const int HW = HH * WW;

    // ---- per-pixel bilinear setup (invariant across channels) ----
    const float fx = flow[(((size_t)b * 2 + 0) * HH + h) * WW + w];
    const float fy = flow[(((size_t)b * 2 + 1) * HH + h) * WW + w];
    const float x = (float)w + fx;
    const float y = (float)h + fy;
    const float x0f = floorf(x);
    const float y0f = floorf(y);
    const int ix0 = (int)x0f;
    const int iy0 = (int)y0f;
    const float ax = x - x0f;
    const float ay = y - y0f;

    float w00 = (1.f - ax) * (1.f - ay);
    float w01 = ax * (1.f - ay);
    float w10 = (1.f - ax) * ay;
    float w11 = ax * ay;

    const bool vx0 = (ix0     >= 0) & (ix0     <= WW - 1);
    const bool vx1 = (ix0 + 1 >= 0) & (ix0 + 1 <= WW - 1);
    const bool vy0 = (iy0     >= 0) & (iy0     <= HH - 1);
    const bool vy1 = (iy0 + 1 >= 0) & (iy0 + 1 <= HH - 1);
    if (!(vx0 & vy0)) w00 = 0.f;
    if (!(vx1 & vy0)) w01 = 0.f;
    if (!(vx0 & vy1)) w10 = 0.f;
    if (!(vx1 & vy1)) w11 = 0.f;

    const int x0c = min(max(ix0, 0), WW - 1);
    const int x1c = min(max(ix0 + 1, 0), WW - 1);
    const int y0c = min(max(iy0, 0), HH - 1);
    const int y1c = min(max(iy0 + 1, 0), HH - 1);

    const int o00 = y0c * WW + x0c;
    const int o01 = y0c * WW + x1c;
    const int o10 = y1c * WW + x0c;
    const int o11 = y1c * WW + x1c;

    const float* lbase = left  + (size_t)b * CC * HW + (size_t)h * WW + w;
    const float* rbase = right + (size_t)b * CC * HW;

    // ---- prologue: fill buffer 0 with chunk 0 ----
    gather_chunk(rbase, buf0, 0, w, HW, o00, o01, o10, o11, w00, w01, w10, w11);

    float acc[WIN];
#pragma unroll
    for (int k = 0; k < WIN; ++k) acc[k] = 0.f;

    const float scale = 1.f / (float)CG;

    // ---- software-pipelined mainloop ----
    for (int c = 0; c < NCHUNK; ++c) {
        __syncthreads();   // chunk c's buffer is complete; previous readers done

        float* cur = (c & 1) ? buf1 : buf0;
        float* nxt = (c & 1) ? buf0 : buf1;

        // Issue next chunk's gathers first — their latency hides behind the
        // consume loop below (no dependence between them).
        if (c + 1 < NCHUNK)
            gather_chunk(rbase, nxt, (c + 1) * CK, w, HW,
                         o00, o01, o10, o11, w00, w01, w10, w11);

        // Consume chunk c: 9-tap sliding window accumulate
#pragma unroll
        for (int cc = 0; cc < CK; ++cc) {
            const float lv = lbase[(size_t)(c * CK + cc) * HW];
            const float* sp = cur + cc * SRS + w;   // taps at sp[0..8]
#pragma unroll
            for (int k = 0; k < WIN; ++k)
                acc[k] = fmaf(lv, sp[k], acc[k]);
        }

        // Group boundary every 2 chunks: write 9 taps (coalesced) and reset
        if (c & 1) {
            const int g = c >> 1;
            float* ob = out + (((size_t)(b * NGRP + g) * WIN) * HH + h) * WW + w;
#pragma unroll
            for (int k = 0; k < WIN; ++k)
                ob[(size_t)k * HW] = acc[k] * scale;
#pragma unroll
            for (int k = 0; k < WIN; ++k) acc[k] = 0.f;
        }
    }
}

extern "C" void kernel_launch(void* const* d_in, const int* in_sizes, int n_in,
                              void* d_out, int out_size)
{
    const float* left  = (const float*)d_in[0];
    const float* right = (const float*)d_in[1];
    const float* flow  = (const float*)d_in[2];
    float* out = (float*)d_out;

    const int smem_bytes = 2 * CK * SRS * (int)sizeof(float);   // 67,584 B
    cudaFuncSetAttribute(crestereo_db_kernel,
                         cudaFuncAttributeMaxDynamicSharedMemorySize, smem_bytes);

    dim3 grid(BB * HH);   // 512 blocks: one per (b, h) row
    dim3 block(WW);       // 256 threads
    crestereo_db_kernel<<<grid, block, smem_bytes>>>(left, right, flow, out);
}

// round 6
// speedup vs baseline: 2.0146x; 1.8497x over previous
#include <cuda_runtime.h>

// Fixed problem shape
#define BB   4
#define CC   256
#define HH   128
#define WW   256
#define NGRP 4
#define CG   64
#define WIN  9
#define CK   32          // channels per smem chunk (same as R1)
#define PW   128         // pixels per block (half row)
#define SRS  136         // smem row: cols 0..135 <-> pixels p0-4 .. p0+131

__global__ __launch_bounds__(128, 6)
void crestereo_half_kernel(const float* __restrict__ left,
                           const float* __restrict__ right,
                           const float* __restrict__ flow,
                           float* __restrict__ out)
{
    __shared__ float srw[CK][SRS];
    __shared__ int   ho[8][4];     // halo gather offsets
    __shared__ float hwt[8][4];    // halo gather weights

    const int bx = blockIdx.x;          // 1024 blocks: [b(2) | h(7) | half(1)]
    const int b  = bx >> 8;
    const int h  = (bx >> 1) & (HH - 1);
    const int p0 = (bx & 1) << 7;       // 0 or 128
    const int t  = threadIdx.x;         // 0..127
    const int w  = p0 + t;              // this thread's pixel
    const int HW = HH * WW;

    // ---- main-pixel bilinear setup (identical math to R1) ----
    const float fx = flow[(((size_t)b * 2 + 0) * HH + h) * WW + w];
    const float fy = flow[(((size_t)b * 2 + 1) * HH + h) * WW + w];
    const float x = (float)w + fx;
    const float y = (float)h + fy;
    const float x0f = floorf(x);
    const float y0f = floorf(y);
    const int ix0 = (int)x0f;
    const int iy0 = (int)y0f;
    const float ax = x - x0f;
    const float ay = y - y0f;

    float w00 = (1.f - ax) * (1.f - ay);
    float w01 = ax * (1.f - ay);
    float w10 = (1.f - ax) * ay;
    float w11 = ax * ay;

    const bool vx0 = (ix0     >= 0) & (ix0     <= WW - 1);
    const bool vx1 = (ix0 + 1 >= 0) & (ix0 + 1 <= WW - 1);
    const bool vy0 = (iy0     >= 0) & (iy0     <= HH - 1);
    const bool vy1 = (iy0 + 1 >= 0) & (iy0 + 1 <= HH - 1);
    if (!(vx0 & vy0)) w00 = 0.f;
    if (!(vx1 & vy0)) w01 = 0.f;
    if (!(vx0 & vy1)) w10 = 0.f;
    if (!(vx1 & vy1)) w11 = 0.f;

    const int x0c = min(max(ix0, 0), WW - 1);
    const int x1c = min(max(ix0 + 1, 0), WW - 1);
    const int y0c = min(max(iy0, 0), HH - 1);
    const int y1c = min(max(iy0 + 1, 0), HH - 1);

    const int o00 = y0c * WW + x0c;
    const int o01 = y0c * WW + x1c;
    const int o10 = y1c * WW + x0c;
    const int o11 = y1c * WW + x1c;

    // ---- halo setup: 8 lanes prepare params for pixels p0-4..p0-1, p0+128..p0+131 ----
    if (t < 8) {
        const int col = (t < 4) ? t : (128 + t);           // smem col 0..3 / 132..135
        int hp = p0 - 4 + col;                             // halo pixel (may be out of row)
        hp = min(max(hp, 0), WW - 1);                      // replicate clamp

        const float hfx = flow[(((size_t)b * 2 + 0) * HH + h) * WW + hp];
        const float hfy = flow[(((size_t)b * 2 + 1) * HH + h) * WW + hp];
        const float hx = (float)hp + hfx;
        const float hy = (float)h  + hfy;
        const float hx0f = floorf(hx);
        const float hy0f = floorf(hy);
        const int hix0 = (int)hx0f;
        const int hiy0 = (int)hy0f;
        const float hax = hx - hx0f;
        const float hay = hy - hy0f;

        float a00 = (1.f - hax) * (1.f - hay);
        float a01 = hax * (1.f - hay);
        float a10 = (1.f - hax) * hay;
        float a11 = hax * hay;

        const bool hvx0 = (hix0     >= 0) & (hix0     <= WW - 1);
        const bool hvx1 = (hix0 + 1 >= 0) & (hix0 + 1 <= WW - 1);
        const bool hvy0 = (hiy0     >= 0) & (hiy0     <= HH - 1);
        const bool hvy1 = (hiy0 + 1 >= 0) & (hiy0 + 1 <= HH - 1);
        if (!(hvx0 & hvy0)) a00 = 0.f;
        if (!(hvx1 & hvy0)) a01 = 0.f;
        if (!(hvx0 & hvy1)) a10 = 0.f;
        if (!(hvx1 & hvy1)) a11 = 0.f;

        const int hx0c = min(max(hix0, 0), WW - 1);
        const int hx1c = min(max(hix0 + 1, 0), WW - 1);
        const int hy0c = min(max(hiy0, 0), HH - 1);
        const int hy1c = min(max(hiy0 + 1, 0), HH - 1);

        ho[t][0] = hy0c * WW + hx0c;
        ho[t][1] = hy0c * WW + hx1c;
        ho[t][2] = hy1c * WW + hx0c;
        ho[t][3] = hy1c * WW + hx1c;
        hwt[t][0] = a00; hwt[t][1] = a01; hwt[t][2] = a10; hwt[t][3] = a11;
    }

    const float* lbase = left  + (size_t)b * CC * HW + (size_t)h * WW + w;
    const float* rbase = right + (size_t)b * CC * HW;

    const int hcol = (t < 4) ? t : (128 + t);   // halo smem col for lanes t<8

    float acc[WIN];

    for (int g = 0; g < NGRP; ++g) {
#pragma unroll
        for (int k = 0; k < WIN; ++k) acc[k] = 0.f;

        for (int ch0 = g * CG; ch0 < (g + 1) * CG; ch0 += CK) {
            __syncthreads();   // orders prologue/previous readers before overwrite

            // halo params (short live range; only lanes t<8 use them)
            int   ho0 = 0, ho1 = 0, ho2 = 0, ho3 = 0;
            float ha0 = 0.f, ha1 = 0.f, ha2 = 0.f, ha3 = 0.f;
            if (t < 8) {
                ho0 = ho[t][0]; ho1 = ho[t][1]; ho2 = ho[t][2]; ho3 = ho[t][3];
                ha0 = hwt[t][0]; ha1 = hwt[t][1]; ha2 = hwt[t][2]; ha3 = hwt[t][3];
            }

            // ---- phase 1: burst-gather CK channels (same shape as R1) ----
#pragma unroll
            for (int cc = 0; cc < CK; ++cc) {
                const float* rb = rbase + (size_t)(ch0 + cc) * HW;
                float v = rb[o00] * w00;
                v = fmaf(rb[o01], w01, v);
                v = fmaf(rb[o10], w10, v);
                v = fmaf(rb[o11], w11, v);
                srw[cc][4 + t] = v;
                if (t < 8) {
                    float vh = rb[ho0] * ha0;
                    vh = fmaf(rb[ho1], ha1, vh);
                    vh = fmaf(rb[ho2], ha2, vh);
                    vh = fmaf(rb[ho3], ha3, vh);
                    srw[cc][hcol] = vh;
                }
            }
            __syncthreads();

            // ---- phase 2: 9-tap sliding-window accumulate ----
#pragma unroll
            for (int cc = 0; cc < CK; ++cc) {
                const float lv = lbase[(size_t)(ch0 + cc) * HW];
                const float* sp = &srw[cc][t];   // taps sp[0..8] == pixels w-4..w+4
#pragma unroll
                for (int k = 0; k < WIN; ++k)
                    acc[k] = fmaf(lv, sp[k], acc[k]);
            }
        }

        // ---- write 9 taps for this group (coalesced, 128-wide) ----
        const float scale = 1.f / (float)CG;
        float* ob = out + (((size_t)(b * NGRP + g) * WIN) * HH + h) * WW + w;
#pragma unroll
        for (int k = 0; k < WIN; ++k)
            ob[(size_t)k * HW] = acc[k] * scale;
    }
}

extern "C" void kernel_launch(void* const* d_in, const int* in_sizes, int n_in,
                              void* d_out, int out_size)
{
    const float* left  = (const float*)d_in[0];
    const float* right = (const float*)d_in[1];
    const float* flow  = (const float*)d_in[2];
    float* out = (float*)d_out;

    dim3 grid(BB * HH * 2);   // 1024 blocks: one per (b, h, half-row)
    dim3 block(PW);           // 128 threads
    crestereo_half_kernel<<<grid, block>>>(left, right, flow, out);
}